// round 2
// baseline (speedup 1.0000x reference)
#include <cuda_runtime.h>
#include <cuda_bf16.h>

typedef unsigned long long ull;

// ---------- packed f32x2 helpers (sm_100+: fma.rn.f32x2 only reachable via PTX) ----------
__device__ __forceinline__ ull pack2(float lo, float hi) {
    ull r;
    asm("mov.b64 %0, {%1, %2};" : "=l"(r)
        : "r"(__float_as_uint(lo)), "r"(__float_as_uint(hi)));
    return r;
}
__device__ __forceinline__ float2 unpack2(ull v) {
    unsigned a, b;
    asm("mov.b64 {%0, %1}, %2;" : "=r"(a), "=r"(b) : "l"(v));
    return make_float2(__uint_as_float(a), __uint_as_float(b));
}
__device__ __forceinline__ ull fma2(ull a, ull b, ull c) {
    ull d;
    asm("fma.rn.f32x2 %0, %1, %2, %3;" : "=l"(d) : "l"(a), "l"(b), "l"(c));
    return d;
}
__device__ __forceinline__ float silu_f(float x) {
    // x * sigmoid(x) = x / (1 + e^-x); MUFU-based (EX2 + RCP), fine for 1e-3 tol.
    return __fdividef(x, 1.0f + __expf(-x));
}

// Problem constants (fixed shapes for this problem)
#define SQ   1024            // S = T*N = 8*128
#define NH   8               // heads
#define HD   64              // hidden
#define BDIM 256

__global__ __launch_bounds__(BDIM, 2)
void shab_kernel(const float* __restrict__ coords,
                 const float* __restrict__ w1, const float* __restrict__ b1,
                 const float* __restrict__ w2, const float* __restrict__ b2,
                 const float* __restrict__ w3, const float* __restrict__ b3,
                 float* __restrict__ out)
{
    // Weights staged in SMEM as packed f32x2 pairs (consecutive cols are pairs).
    // Layer1 repacked row-major per output-pair: [kp][q0..q8, bias] = 10 ull = 80B
    // (16B-aligned rows -> 5x LDS.128 per kp instead of 10 scalar LDS).
    __shared__ __align__(16) ull sw1t[32 * 10];
    __shared__ __align__(16) ull sw2p[64 * 32];   // w2 [64][64] -> [64][32] pairs
    __shared__ __align__(16) ull sb2p[32];
    __shared__ __align__(16) ull sw3p[64 * 4];    // w3 [64][8]  -> [64][4] pairs
    __shared__ __align__(16) ull sb3p[4];

    const int tid = threadIdx.x;
    {
        const ull* g1 = (const ull*)w1;     // [9][32] pairs, row q
        const ull* g2 = (const ull*)w2;
        const ull* g3 = (const ull*)w3;
        for (int idx = tid; idx < 9 * 32; idx += BDIM) {
            int q = idx >> 5, kp = idx & 31;
            sw1t[kp * 10 + q] = g1[idx];
        }
        for (int idx = tid; idx < 64 * 32; idx += BDIM) sw2p[idx] = g2[idx];
        for (int idx = tid; idx < 64 * 4;  idx += BDIM) sw3p[idx] = g3[idx];
        if (tid < 32) {
            sw1t[tid * 10 + 9] = ((const ull*)b1)[tid];
            sb2p[tid] = ((const ull*)b2)[tid];
        }
        if (tid < 4) sb3p[tid] = ((const ull*)b3)[tid];
    }
    __syncthreads();

    // blockIdx.x = b*4096 + i*4 + jt   (B=2, S=1024, 4 j-tiles of 256)
    const int blk = blockIdx.x;
    const int jt  = blk & 3;
    const int i   = (blk >> 2) & (SQ - 1);
    const int b   = blk >> 12;
    const int j   = jt * BDIM + tid;

    const float* cb = coords + (size_t)b * SQ * 3;
    const float xi = cb[i * 3 + 0], yi = cb[i * 3 + 1], zi = cb[i * 3 + 2];
    const float xj = cb[j * 3 + 0], yj = cb[j * 3 + 1], zj = cb[j * 3 + 2];

    // rel = c_i - c_j ; double-normalize exactly like the reference
    float rx = xi - xj, ry = yi - yj, rz = zi - zj;
    float nrm = sqrtf(rx * rx + ry * ry + rz * rz);
    float inv1 = __fdividef(1.0f, nrm + 1e-6f);
    float ux = rx * inv1, uy = ry * inv1, uz = rz * inv1;
    float un = nrm * inv1;                       // == |u|
    float inv2 = __fdividef(1.0f, fmaxf(un, 1e-6f));
    ux *= inv2; uy *= inv2; uz *= inv2;

    // e3nn real SH, l=0..2, integral normalization, e3nn xyz ordering
    float sh[9];
    sh[0] = 0.28209479177387814f;
    sh[1] = 0.4886025119029199f * ux;
    sh[2] = 0.4886025119029199f * uy;
    sh[3] = 0.4886025119029199f * uz;
    sh[4] = 1.0925484305920792f * ux * uz;
    sh[5] = 1.0925484305920792f * ux * uy;
    sh[6] = 0.6307831305050401f * (uy * uy - 0.5f * (ux * ux + uz * uz));
    sh[7] = 1.0925484305920792f * uy * uz;
    sh[8] = 0.5462742152960396f * (uz * uz - ux * ux);

    ull sh2[9];
    #pragma unroll
    for (int q = 0; q < 9; q++) sh2[q] = pack2(sh[q], sh[q]);

    // Layer-2 pre-activation accumulators: 64 floats as 32 packed f32x2 (in regs)
    ull acc2[32];
    #pragma unroll
    for (int m = 0; m < 32; m++) acc2[m] = sb2p[m];

    // Fused layer1 -> silu -> rank-1 update of layer2.
    // kp indexes pairs of layer-1 outputs (h[2kp], h[2kp+1]).
    #pragma unroll 2
    for (int kp = 0; kp < 32; kp++) {
        const ulonglong2* w1r = (const ulonglong2*)&sw1t[kp * 10];
        ulonglong2 p0 = w1r[0], p1 = w1r[1], p2 = w1r[2], p3 = w1r[3], p4 = w1r[4];
        ull a = p4.y;                         // bias pair
        a = fma2(p0.x, sh2[0], a);
        a = fma2(p0.y, sh2[1], a);
        a = fma2(p1.x, sh2[2], a);
        a = fma2(p1.y, sh2[3], a);
        a = fma2(p2.x, sh2[4], a);
        a = fma2(p2.y, sh2[5], a);
        a = fma2(p3.x, sh2[6], a);
        a = fma2(p3.y, sh2[7], a);
        a = fma2(p4.x, sh2[8], a);

        float2 hv = unpack2(a);
        float h0 = silu_f(hv.x);
        float h1 = silu_f(hv.y);
        ull h0p = pack2(h0, h0);
        ull h1p = pack2(h1, h1);

        const ulonglong2* r0 = (const ulonglong2*)&sw2p[(2 * kp)     * 32];
        const ulonglong2* r1 = (const ulonglong2*)&sw2p[(2 * kp + 1) * 32];
        #pragma unroll
        for (int m = 0; m < 16; m++) {
            ulonglong2 wa = r0[m];
            acc2[2 * m]     = fma2(wa.x, h0p, acc2[2 * m]);
            acc2[2 * m + 1] = fma2(wa.y, h0p, acc2[2 * m + 1]);
        }
        #pragma unroll
        for (int m = 0; m < 16; m++) {
            ulonglong2 wb = r1[m];
            acc2[2 * m]     = fma2(wb.x, h1p, acc2[2 * m]);
            acc2[2 * m + 1] = fma2(wb.y, h1p, acc2[2 * m + 1]);
        }
    }

    // Epilogue: silu(layer2) -> layer3 (64 -> 8), packed
    ull out4[4];
    #pragma unroll
    for (int p = 0; p < 4; p++) out4[p] = sb3p[p];

    #pragma unroll
    for (int m2 = 0; m2 < 32; m2++) {
        float2 v = unpack2(acc2[m2]);
        float s0 = silu_f(v.x);
        float s1 = silu_f(v.y);
        ull s0p = pack2(s0, s0);
        ull s1p = pack2(s1, s1);
        const ulonglong2* r0 = (const ulonglong2*)&sw3p[(2 * m2)     * 4];
        const ulonglong2* r1 = (const ulonglong2*)&sw3p[(2 * m2 + 1) * 4];
        ulonglong2 wa0 = r0[0], wa1 = r0[1];
        ulonglong2 wb0 = r1[0], wb1 = r1[1];
        out4[0] = fma2(wa0.x, s0p, out4[0]);
        out4[1] = fma2(wa0.y, s0p, out4[1]);
        out4[2] = fma2(wa1.x, s0p, out4[2]);
        out4[3] = fma2(wa1.y, s0p, out4[3]);
        out4[0] = fma2(wb0.x, s1p, out4[0]);
        out4[1] = fma2(wb0.y, s1p, out4[1]);
        out4[2] = fma2(wb1.x, s1p, out4[2]);
        out4[3] = fma2(wb1.y, s1p, out4[3]);
    }

    // out[b][h][i][j], h-stride = S*S; consecutive j across threads -> coalesced
    const size_t SS = (size_t)SQ * SQ;
    size_t base = (size_t)(b * NH) * SS + (size_t)i * SQ + (size_t)j;
    float2 v;
    v = unpack2(out4[0]); out[base + 0 * SS] = v.x; out[base + 1 * SS] = v.y;
    v = unpack2(out4[1]); out[base + 2 * SS] = v.x; out[base + 3 * SS] = v.y;
    v = unpack2(out4[2]); out[base + 4 * SS] = v.x; out[base + 5 * SS] = v.y;
    v = unpack2(out4[3]); out[base + 6 * SS] = v.x; out[base + 7 * SS] = v.y;
}

extern "C" void kernel_launch(void* const* d_in, const int* in_sizes, int n_in,
                              void* d_out, int out_size) {
    const float* coords = (const float*)d_in[0];
    const float* w1     = (const float*)d_in[1];
    const float* b1     = (const float*)d_in[2];
    const float* w2     = (const float*)d_in[3];
    const float* b2     = (const float*)d_in[4];
    const float* w3     = (const float*)d_in[5];
    const float* b3     = (const float*)d_in[6];
    float* out = (float*)d_out;

    // grid: B(2) * S(1024) * 4 j-tiles = 8192 blocks of 256 threads
    shab_kernel<<<8192, BDIM>>>(coords, w1, b1, w2, b2, w3, b3, out);
}

// round 5
// speedup vs baseline: 1.0688x; 1.0688x over previous
#include <cuda_runtime.h>
#include <cuda_bf16.h>

typedef unsigned long long ull;

// ---------- packed f32x2 helpers (sm_100+: fma.rn.f32x2 only via PTX) ----------
__device__ __forceinline__ ull pack2(float lo, float hi) {
    ull r;
    asm("mov.b64 %0, {%1, %2};" : "=l"(r)
        : "r"(__float_as_uint(lo)), "r"(__float_as_uint(hi)));
    return r;
}
__device__ __forceinline__ float2 unpack2(ull v) {
    unsigned a, b;
    asm("mov.b64 {%0, %1}, %2;" : "=r"(a), "=r"(b) : "l"(v));
    return make_float2(__uint_as_float(a), __uint_as_float(b));
}
__device__ __forceinline__ ull fma2(ull a, ull b, ull c) {
    ull d;
    asm("fma.rn.f32x2 %0, %1, %2, %3;" : "=l"(d) : "l"(a), "l"(b), "l"(c));
    return d;
}
__device__ __forceinline__ float silu_f(float x) {
    return __fdividef(x, 1.0f + __expf(-x));
}

#define SQ   1024
#define NH   8
#define BDIM 256

// SMEM layout with +16B shims so even/odd channel-halves hit disjoint banks:
//  sw1t[k][10] : (w1[q][k],w1[q][k]) duplicated packs, q=0..8, then bias pack. Uniform broadcast.
//  sw2s[r][36] : row r of w2; half0 pairs at cols 0..15, half1 at cols 18..33 (144B offset == 16 mod 128).
//  sw3s        : half h base = h*130 ull (1040B == 16 mod 128); row rr at +rr*4, 4 ull per row.
//  sb2s[36]    : layer-2 bias pairs, same half shim.

__global__ __launch_bounds__(BDIM, 2)
void shab_kernel(const float* __restrict__ coords,
                 const float* __restrict__ w1, const float* __restrict__ b1,
                 const float* __restrict__ w2, const float* __restrict__ b2,
                 const float* __restrict__ w3, const float* __restrict__ b3,
                 float* __restrict__ out)
{
    __shared__ __align__(16) ull sw1t[64 * 10];
    __shared__ __align__(16) ull sw2s[64 * 36];
    __shared__ __align__(16) ull sw3s[2 * 130];
    __shared__ __align__(16) ull sb2s[36];
    __shared__ __align__(16) ull sb3p[4];

    const int tid = threadIdx.x;
    {
        const ull* g2 = (const ull*)w2;
        for (int idx = tid; idx < 64 * 32; idx += BDIM) {
            int r = idx >> 5, c = idx & 31;
            sw2s[r * 36 + (c < 16 ? c : c + 2)] = g2[idx];
        }
        const ull* g3 = (const ull*)w3;
        for (int idx = tid; idx < 64 * 4; idx += BDIM) {
            int r = idx >> 2, c = idx & 3;
            sw3s[(r >> 5) * 130 + (r & 31) * 4 + c] = g3[idx];
        }
        if (tid < 64) {
            #pragma unroll
            for (int q = 0; q < 9; q++) {
                float v = w1[q * 64 + tid];
                sw1t[tid * 10 + q] = pack2(v, v);
            }
            float bv = b1[tid];
            sw1t[tid * 10 + 9] = pack2(bv, bv);
        }
        if (tid < 32) sb2s[tid < 16 ? tid : tid + 2] = ((const ull*)b2)[tid];
        if (tid < 4)  sb3p[tid] = ((const ull*)b3)[tid];
    }
    __syncthreads();

    // blockIdx.x = b*4096 + i*4 + jt ; thread handles pairs (i,j0),(i,j0+1), channel half = tid&1
    const int blk  = blockIdx.x;
    const int jt   = blk & 3;
    const int i    = (blk >> 2) & (SQ - 1);
    const int b    = blk >> 12;
    const int half = tid & 1;
    const int j0   = jt * BDIM + (tid & ~1);

    const float* cb = coords + (size_t)b * SQ * 3;
    const float xi = cb[i * 3 + 0], yi = cb[i * 3 + 1], zi = cb[i * 3 + 2];

    // SH for both pairs, packed lanes = (pair0, pair1)
    ull sh2[9];
    {
        float shp[2][9];
        #pragma unroll
        for (int p = 0; p < 2; p++) {
            int j = j0 + p;
            float rx = xi - cb[j * 3 + 0];
            float ry = yi - cb[j * 3 + 1];
            float rz = zi - cb[j * 3 + 2];
            float nrm = sqrtf(rx * rx + ry * ry + rz * rz);
            float inv1 = __fdividef(1.0f, nrm + 1e-6f);
            float ux = rx * inv1, uy = ry * inv1, uz = rz * inv1;
            float un = nrm * inv1;
            float inv2 = __fdividef(1.0f, fmaxf(un, 1e-6f));
            ux *= inv2; uy *= inv2; uz *= inv2;
            shp[p][0] = 0.28209479177387814f;
            shp[p][1] = 0.4886025119029199f * ux;
            shp[p][2] = 0.4886025119029199f * uy;
            shp[p][3] = 0.4886025119029199f * uz;
            shp[p][4] = 1.0925484305920792f * ux * uz;
            shp[p][5] = 1.0925484305920792f * ux * uy;
            shp[p][6] = 0.6307831305050401f * (uy * uy - 0.5f * (ux * ux + uz * uz));
            shp[p][7] = 1.0925484305920792f * uy * uz;
            shp[p][8] = 0.5462742152960396f * (uz * uz - ux * ux);
        }
        #pragma unroll
        for (int q = 0; q < 9; q++) sh2[q] = pack2(shp[0][q], shp[1][q]);
    }

    // Layer-2 accumulators: 2 pairs x 16 channel-pairs (owned half)
    ull acc0[16], acc1[16];
    {
        const ull* sb2h = sb2s + half * 18;
        #pragma unroll
        for (int c = 0; c < 16; c++) { acc0[c] = sb2h[c]; acc1[c] = acc0[c]; }
    }

    const ull* w2h = sw2s + half * 18;

    #pragma unroll 4
    for (int k = 0; k < 64; k++) {
        // layer1 channel k for BOTH pairs in one packed chain
        const ulonglong2* wr = (const ulonglong2*)(sw1t + k * 10);
        ulonglong2 p0 = wr[0], p1 = wr[1], p2 = wr[2], p3 = wr[3], p4 = wr[4];
        ull a = p4.y;                       // (bias, bias)
        a = fma2(p0.x, sh2[0], a);
        a = fma2(p0.y, sh2[1], a);
        a = fma2(p1.x, sh2[2], a);
        a = fma2(p1.y, sh2[3], a);
        a = fma2(p2.x, sh2[4], a);
        a = fma2(p2.y, sh2[5], a);
        a = fma2(p3.x, sh2[6], a);
        a = fma2(p3.y, sh2[7], a);
        a = fma2(p4.x, sh2[8], a);

        float2 hv = unpack2(a);
        float h0 = silu_f(hv.x);            // pair0
        float h1 = silu_f(hv.y);            // pair1
        ull h0p = pack2(h0, h0);
        ull h1p = pack2(h1, h1);

        // layer2 row k, owned 32 channels (16 ull = 8 LDS.128), reused for both pairs
        const ulonglong2* r = (const ulonglong2*)(w2h + k * 36);
        #pragma unroll
        for (int m = 0; m < 8; m++) {
            ulonglong2 w = r[m];
            acc0[2 * m]     = fma2(w.x, h0p, acc0[2 * m]);
            acc0[2 * m + 1] = fma2(w.y, h0p, acc0[2 * m + 1]);
            acc1[2 * m]     = fma2(w.x, h1p, acc1[2 * m]);
            acc1[2 * m + 1] = fma2(w.y, h1p, acc1[2 * m + 1]);
        }
    }

    // Epilogue: silu -> layer3 partials over owned channels (bias only on half 0)
    ull o0[4], o1[4];
    #pragma unroll
    for (int kk = 0; kk < 4; kk++) {
        ull bi = (half == 0) ? sb3p[kk] : 0ULL;
        o0[kk] = bi; o1[kk] = bi;
    }

    const ull* w3h = sw3s + half * 130;
    #pragma unroll 4
    for (int c = 0; c < 16; c++) {
        float2 v0 = unpack2(acc0[c]);
        float2 v1 = unpack2(acc1[c]);
        float s00 = silu_f(v0.x), s01 = silu_f(v0.y);   // pair0: ch 2c, 2c+1
        float s10 = silu_f(v1.x), s11 = silu_f(v1.y);   // pair1
        ull s00p = pack2(s00, s00), s01p = pack2(s01, s01);
        ull s10p = pack2(s10, s10), s11p = pack2(s11, s11);

        const ulonglong2* q0 = (const ulonglong2*)(w3h + (2 * c) * 4);
        const ulonglong2* q1 = (const ulonglong2*)(w3h + (2 * c + 1) * 4);
        ulonglong2 a0 = q0[0], a1 = q0[1];
        ulonglong2 c0 = q1[0], c1 = q1[1];

        o0[0] = fma2(a0.x, s00p, o0[0]); o0[1] = fma2(a0.y, s00p, o0[1]);
        o0[2] = fma2(a1.x, s00p, o0[2]); o0[3] = fma2(a1.y, s00p, o0[3]);
        o0[0] = fma2(c0.x, s01p, o0[0]); o0[1] = fma2(c0.y, s01p, o0[1]);
        o0[2] = fma2(c1.x, s01p, o0[2]); o0[3] = fma2(c1.y, s01p, o0[3]);

        o1[0] = fma2(a0.x, s10p, o1[0]); o1[1] = fma2(a0.y, s10p, o1[1]);
        o1[2] = fma2(a1.x, s10p, o1[2]); o1[3] = fma2(a1.y, s10p, o1[3]);
        o1[0] = fma2(c0.x, s11p, o1[0]); o1[1] = fma2(c0.y, s11p, o1[1]);
        o1[2] = fma2(c1.x, s11p, o1[2]); o1[3] = fma2(c1.y, s11p, o1[3]);
    }

    // Cross-half combine: lane keeps the pair it writes (pair = half), receives the
    // neighbor's partial for that pair via shfl_xor(1).
    float res[8];
    #pragma unroll
    for (int kk = 0; kk < 4; kk++) {
        float2 vk = unpack2(half ? o1[kk] : o0[kk]);   // keep: my partial of my pair
        float2 vs = unpack2(half ? o0[kk] : o1[kk]);   // send: my partial of neighbor's pair
        res[2 * kk]     = vk.x + __shfl_xor_sync(0xFFFFFFFFu, vs.x, 1);
        res[2 * kk + 1] = vk.y + __shfl_xor_sync(0xFFFFFFFFu, vs.y, 1);
    }

    // j written = j0 + half = jt*256 + tid  -> fully coalesced per head
    const size_t SS = (size_t)SQ * SQ;
    const int j = jt * BDIM + tid;
    size_t base = (size_t)(b * NH) * SS + (size_t)i * SQ + (size_t)j;
    #pragma unroll
    for (int h = 0; h < 8; h++) out[base + (size_t)h * SS] = res[h];
}

extern "C" void kernel_launch(void* const* d_in, const int* in_sizes, int n_in,
                              void* d_out, int out_size) {
    const float* coords = (const float*)d_in[0];
    const float* w1     = (const float*)d_in[1];
    const float* b1     = (const float*)d_in[2];
    const float* w2     = (const float*)d_in[3];
    const float* b2     = (const float*)d_in[4];
    const float* w3     = (const float*)d_in[5];
    const float* b3     = (const float*)d_in[6];
    float* out = (float*)d_out;

    shab_kernel<<<8192, BDIM>>>(coords, w1, b1, w2, b2, w3, b3, out);
}

// round 10
// speedup vs baseline: 2.2925x; 2.1450x over previous
#include <cuda_runtime.h>
#include <cuda_bf16.h>
#include <cstdint>

#define SQ 1024
#define NH 8

// ---------------- helpers ----------------
__device__ __forceinline__ float silu_f(float x) {
    return __fdividef(x, 1.0f + __expf(-x));   // validated 2e-7 end-to-end
}
__device__ __forceinline__ uint32_t pk_hi(float a, float b) {
    __nv_bfloat162 t = __floats2bfloat162_rn(a, b);   // a -> low half
    return *(uint32_t*)&t;
}
__device__ __forceinline__ uint32_t pk_lo(float a, float b) {
    float ra = a - __bfloat162float(__float2bfloat16_rn(a));
    float rb = b - __bfloat162float(__float2bfloat16_rn(b));
    __nv_bfloat162 t = __floats2bfloat162_rn(ra, rb);
    return *(uint32_t*)&t;
}
// split two f32 into packed bf16 hi word + lo (residual) word
__device__ __forceinline__ void split2(float a, float b, uint32_t& hi, uint32_t& lo) {
    hi = pk_hi(a, b);
    lo = pk_lo(a, b);
}
// m16n8k16 bf16 MMA, D += A*B (fp32 accum)
__device__ __forceinline__ void mma_bf16(float* d, const uint32_t* a, uint32_t b0, uint32_t b1) {
    asm volatile(
        "mma.sync.aligned.m16n8k16.row.col.f32.bf16.bf16.f32 "
        "{%0,%1,%2,%3}, {%4,%5,%6,%7}, {%8,%9}, {%0,%1,%2,%3};"
        : "+f"(d[0]), "+f"(d[1]), "+f"(d[2]), "+f"(d[3])
        : "r"(a[0]), "r"(a[1]), "r"(a[2]), "r"(a[3]), "r"(b0), "r"(b1));
}

// ---------------- kernel ----------------
// Block: 256 threads = 8 warps; each warp does a 16-pair tile (M=16, hidden N=64).
// Grid: (B=2) x (i=1024) x (8 j-subtiles of 128) = 16384 blocks.
__global__ __launch_bounds__(256)
void shab_mma_kernel(const float* __restrict__ coords,
                     const float* __restrict__ w1, const float* __restrict__ b1,
                     const float* __restrict__ w2, const float* __restrict__ b2,
                     const float* __restrict__ w3, const float* __restrict__ b3,
                     float* __restrict__ out)
{
    // B fragments pre-packed per lane: uint4 = {b0_hi, b1_hi, b0_lo, b1_lo}
    __shared__ uint4 sB1[8][32];        // layer1: K=16(1 chunk) x 8 n-blocks
    __shared__ uint4 sB2[4][8][32];     // layer2: 4 k-chunks x 8 n-blocks
    __shared__ uint4 sB3[4][32];        // layer3: 4 k-chunks x 1 n-block (N=8)
    __shared__ uint32_t stg[8][2][16][8];  // per-warp A1 staging: [hi/lo][pair][kword]
    __shared__ float sb2[64], sb3[8];

    const int tid = threadIdx.x;

    // ---- prologue: pack weight B-fragments (bf16 hi/lo) ----
    // layer1: W1eff[k][n]: k<9 -> w1, k==9 -> b1 (bias slot), else 0. 256 entries.
    {
        int idx = tid;                      // exactly one per thread
        int nb = idx >> 5, lane = idx & 31;
        int n = nb * 8 + (lane >> 2);
        int k0 = (lane & 3) * 2;
        float v[4];
        #pragma unroll
        for (int q = 0; q < 4; q++) {
            int k = k0 + (q & 1) + (q >> 1) * 8;
            v[q] = (k < 9) ? w1[k * 64 + n] : ((k == 9) ? b1[n] : 0.0f);
        }
        sB1[nb][lane] = make_uint4(pk_hi(v[0], v[1]), pk_hi(v[2], v[3]),
                                   pk_lo(v[0], v[1]), pk_lo(v[2], v[3]));
    }
    for (int idx = tid; idx < 1024; idx += 256) {
        int kc = idx >> 8, rem = idx & 255;
        int nb = rem >> 5, lane = rem & 31;
        int n = nb * 8 + (lane >> 2);
        int k0 = kc * 16 + (lane & 3) * 2;
        float v0 = w2[k0 * 64 + n],       v1 = w2[(k0 + 1) * 64 + n];
        float v2 = w2[(k0 + 8) * 64 + n], v3 = w2[(k0 + 9) * 64 + n];
        sB2[kc][nb][lane] = make_uint4(pk_hi(v0, v1), pk_hi(v2, v3),
                                       pk_lo(v0, v1), pk_lo(v2, v3));
    }
    if (tid < 128) {
        int kc = tid >> 5, lane = tid & 31;
        int n = lane >> 2;
        int k0 = kc * 16 + (lane & 3) * 2;
        float v0 = w3[k0 * 8 + n],       v1 = w3[(k0 + 1) * 8 + n];
        float v2 = w3[(k0 + 8) * 8 + n], v3 = w3[(k0 + 9) * 8 + n];
        sB3[kc][lane] = make_uint4(pk_hi(v0, v1), pk_hi(v2, v3),
                                   pk_lo(v0, v1), pk_lo(v2, v3));
    }
    if (tid < 64) sb2[tid] = b2[tid];
    if (tid >= 64 && tid < 72) sb3[tid - 64] = b3[tid - 64];
    __syncthreads();

    // ---- tile coordinates ----
    const int blk = blockIdx.x;
    const int jt8 = blk & 7;
    const int i   = (blk >> 3) & (SQ - 1);
    const int b   = blk >> 13;
    const int w   = tid >> 5;
    const int lane = tid & 31;
    const int j0  = jt8 * 128 + w * 16;

    const float* cb = coords + (size_t)b * SQ * 3;

    // ---- SH for this warp's 16 pairs (lanes 0..15), staged as A1 fragments ----
    if (lane < 16) {
        const float xi = cb[i * 3 + 0], yi = cb[i * 3 + 1], zi = cb[i * 3 + 2];
        const int j = j0 + lane;
        float rx = xi - cb[j * 3 + 0];
        float ry = yi - cb[j * 3 + 1];
        float rz = zi - cb[j * 3 + 2];
        float nrm = sqrtf(rx * rx + ry * ry + rz * rz);
        float inv1 = __fdividef(1.0f, nrm + 1e-6f);
        float ux = rx * inv1, uy = ry * inv1, uz = rz * inv1;
        float un = nrm * inv1;
        float inv2 = __fdividef(1.0f, fmaxf(un, 1e-6f));
        ux *= inv2; uy *= inv2; uz *= inv2;
        float v[10];
        v[0] = 0.28209479177387814f;
        v[1] = 0.4886025119029199f * ux;
        v[2] = 0.4886025119029199f * uy;
        v[3] = 0.4886025119029199f * uz;
        v[4] = 1.0925484305920792f * ux * uz;
        v[5] = 1.0925484305920792f * ux * uy;
        v[6] = 0.6307831305050401f * (uy * uy - 0.5f * (ux * ux + uz * uz));
        v[7] = 1.0925484305920792f * uy * uz;
        v[8] = 0.5462742152960396f * (uz * uz - ux * ux);
        v[9] = 1.0f;                          // bias slot
        #pragma unroll
        for (int kw = 0; kw < 5; kw++) {
            stg[w][0][lane][kw] = pk_hi(v[2 * kw], v[2 * kw + 1]);
            stg[w][1][lane][kw] = pk_lo(v[2 * kw], v[2 * kw + 1]);
        }
        #pragma unroll
        for (int kw = 5; kw < 8; kw++) {
            stg[w][0][lane][kw] = 0u;
            stg[w][1][lane][kw] = 0u;
        }
    }
    __syncwarp();

    const int r0 = lane >> 2;     // row group
    const int qk = lane & 3;      // k/col group

    // A1 fragments (hi + lo)
    uint32_t a1h[4], a1l[4];
    a1h[0] = stg[w][0][r0][qk];     a1h[1] = stg[w][0][r0 + 8][qk];
    a1h[2] = stg[w][0][r0][qk + 4]; a1h[3] = stg[w][0][r0 + 8][qk + 4];
    a1l[0] = stg[w][1][r0][qk];     a1l[1] = stg[w][1][r0 + 8][qk];
    a1l[2] = stg[w][1][r0][qk + 4]; a1l[3] = stg[w][1][r0 + 8][qk + 4];

    // ---- GEMM1: D1[16x64] = A1 @ W1 (3-term split), nb pairs for ILP ----
    float d1[8][4];
    #pragma unroll
    for (int nbp = 0; nbp < 4; nbp++) {
        const int nb0 = 2 * nbp, nb1 = nb0 + 1;
        uint4 f0 = sB1[nb0][lane], f1 = sB1[nb1][lane];
        float* da = d1[nb0];
        float* db = d1[nb1];
        da[0] = da[1] = da[2] = da[3] = 0.0f;
        db[0] = db[1] = db[2] = db[3] = 0.0f;
        mma_bf16(da, a1h, f0.x, f0.y);
        mma_bf16(db, a1h, f1.x, f1.y);
        mma_bf16(da, a1l, f0.x, f0.y);
        mma_bf16(db, a1l, f1.x, f1.y);
        mma_bf16(da, a1h, f0.z, f0.w);
        mma_bf16(db, a1h, f1.z, f1.w);
    }

    // ---- act1: silu(D1) -> A2 fragments (D-frag == A-frag layout) ----
    uint32_t a2h[4][4], a2l[4][4];
    #pragma unroll
    for (int kc = 0; kc < 4; kc++) {
        float* pa = d1[2 * kc];
        float* pb = d1[2 * kc + 1];
        split2(silu_f(pa[0]), silu_f(pa[1]), a2h[kc][0], a2l[kc][0]);
        split2(silu_f(pa[2]), silu_f(pa[3]), a2h[kc][1], a2l[kc][1]);
        split2(silu_f(pb[0]), silu_f(pb[1]), a2h[kc][2], a2l[kc][2]);
        split2(silu_f(pb[2]), silu_f(pb[3]), a2h[kc][3], a2l[kc][3]);
    }

    // ---- GEMM2: D2 = act1 @ W2 (+b2 via accumulator init) ----
    float d2[8][4];
    #pragma unroll
    for (int nbp = 0; nbp < 4; nbp++) {
        const int nb0 = 2 * nbp, nb1 = nb0 + 1;
        float2 ba = *(const float2*)&sb2[nb0 * 8 + qk * 2];
        float2 bb = *(const float2*)&sb2[nb1 * 8 + qk * 2];
        float* da = d2[nb0];
        float* db = d2[nb1];
        da[0] = ba.x; da[1] = ba.y; da[2] = ba.x; da[3] = ba.y;
        db[0] = bb.x; db[1] = bb.y; db[2] = bb.x; db[3] = bb.y;
        #pragma unroll
        for (int kc = 0; kc < 4; kc++) {
            uint4 f0 = sB2[kc][nb0][lane], f1 = sB2[kc][nb1][lane];
            mma_bf16(da, a2h[kc], f0.x, f0.y);
            mma_bf16(db, a2h[kc], f1.x, f1.y);
            mma_bf16(da, a2l[kc], f0.x, f0.y);
            mma_bf16(db, a2l[kc], f1.x, f1.y);
            mma_bf16(da, a2h[kc], f0.z, f0.w);
            mma_bf16(db, a2h[kc], f1.z, f1.w);
        }
    }

    // ---- act2: silu(D2) -> A3 fragments ----
    uint32_t a3h[4][4], a3l[4][4];
    #pragma unroll
    for (int kc = 0; kc < 4; kc++) {
        float* pa = d2[2 * kc];
        float* pb = d2[2 * kc + 1];
        split2(silu_f(pa[0]), silu_f(pa[1]), a3h[kc][0], a3l[kc][0]);
        split2(silu_f(pa[2]), silu_f(pa[3]), a3h[kc][1], a3l[kc][1]);
        split2(silu_f(pb[0]), silu_f(pb[1]), a3h[kc][2], a3l[kc][2]);
        split2(silu_f(pb[2]), silu_f(pb[3]), a3h[kc][3], a3l[kc][3]);
    }

    // ---- GEMM3: D3[16x8] = act2 @ W3 (+b3) ----
    float2 b3v = *(const float2*)&sb3[qk * 2];
    float d3[4] = {b3v.x, b3v.y, b3v.x, b3v.y};
    #pragma unroll
    for (int kc = 0; kc < 4; kc++) {
        uint4 f = sB3[kc][lane];
        mma_bf16(d3, a3h[kc], f.x, f.y);
        mma_bf16(d3, a3l[kc], f.x, f.y);
        mma_bf16(d3, a3h[kc], f.z, f.w);
    }

    // ---- store: D3 c0/c1 -> (j0+r0, heads 2qk,2qk+1); c2/c3 -> row +8 ----
    const size_t SS = (size_t)SQ * SQ;
    const int jr = j0 + r0;
    size_t base = ((size_t)(b * NH + qk * 2)) * SS + (size_t)i * SQ + (size_t)jr;
    out[base]          = d3[0];
    out[base + SS]     = d3[1];
    out[base + 8]      = d3[2];
    out[base + SS + 8] = d3[3];
}

extern "C" void kernel_launch(void* const* d_in, const int* in_sizes, int n_in,
                              void* d_out, int out_size) {
    const float* coords = (const float*)d_in[0];
    const float* w1     = (const float*)d_in[1];
    const float* b1     = (const float*)d_in[2];
    const float* w2     = (const float*)d_in[3];
    const float* b2     = (const float*)d_in[4];
    const float* w3     = (const float*)d_in[5];
    const float* b3     = (const float*)d_in[6];
    float* out = (float*)d_out;

    // 2 (batch) * 1024 (i) * 8 (j subtiles of 128) = 16384 blocks, 8 warps each
    shab_mma_kernel<<<16384, 256>>>(coords, w1, b1, w2, b2, w3, b3, out);
}

// round 15
// speedup vs baseline: 2.2974x; 1.0021x over previous
#include <cuda_runtime.h>
#include <cuda_bf16.h>
#include <cstdint>

#define SQ 1024
#define NH 8

// ---------------- helpers ----------------
__device__ __forceinline__ float silu_f(float x) {
    return __fdividef(x, 1.0f + __expf(-x));
}
__device__ __forceinline__ uint32_t pk_hi(float a, float b) {
    __nv_bfloat162 t = __floats2bfloat162_rn(a, b);   // a -> low half
    return *(uint32_t*)&t;
}
__device__ __forceinline__ uint32_t pk_lo(float a, float b) {
    float ra = a - __bfloat162float(__float2bfloat16_rn(a));
    float rb = b - __bfloat162float(__float2bfloat16_rn(b));
    __nv_bfloat162 t = __floats2bfloat162_rn(ra, rb);
    return *(uint32_t*)&t;
}
__device__ __forceinline__ void split2(float a, float b, uint32_t& hi, uint32_t& lo) {
    hi = pk_hi(a, b);
    lo = pk_lo(a, b);
}
// m16n8k16 bf16 MMA, D += A*B (fp32 accum)
__device__ __forceinline__ void mma_bf16(float* d, const uint32_t* a, uint32_t b0, uint32_t b1) {
    asm volatile(
        "mma.sync.aligned.m16n8k16.row.col.f32.bf16.bf16.f32 "
        "{%0,%1,%2,%3}, {%4,%5,%6,%7}, {%8,%9}, {%0,%1,%2,%3};"
        : "+f"(d[0]), "+f"(d[1]), "+f"(d[2]), "+f"(d[3])
        : "r"(a[0]), "r"(a[1]), "r"(a[2]), "r"(a[3]), "r"(b0), "r"(b1));
}

// ---------------- kernel ----------------
// Block: 128 threads = 4 warps; each warp does a 32-pair tile (M=32 via two
// 16-row fragment sets sharing every B-fragment load).
// Grid: (B=2) x (i=1024) x (8 j-subtiles of 128) = 16384 blocks.
__global__ __launch_bounds__(128)
void shab_mma_kernel(const float* __restrict__ coords,
                     const float* __restrict__ w1, const float* __restrict__ b1,
                     const float* __restrict__ w2, const float* __restrict__ b2,
                     const float* __restrict__ w3, const float* __restrict__ b3,
                     float* __restrict__ out)
{
    // B fragments pre-packed per lane: uint4 = {b0_hi, b1_hi, b0_lo, b1_lo}
    __shared__ uint4 sB1[8][32];        // layer1: K=16(1 chunk) x 8 n-blocks
    __shared__ uint4 sB2[4][8][32];     // layer2: 4 k-chunks x 8 n-blocks
    __shared__ uint4 sB3[4][32];        // layer3: 4 k-chunks x 1 n-block (N=8)
    __shared__ uint32_t stg[4][2][32][8];  // per-warp A1 staging: [hi/lo][pair][kword]
    __shared__ float sb2[64], sb3[8];

    const int tid = threadIdx.x;

    // ---- prologue: pack weight B-fragments (bf16 hi/lo) ----
    for (int idx = tid; idx < 256; idx += 128) {
        int nb = idx >> 5, lane = idx & 31;
        int n = nb * 8 + (lane >> 2);
        int k0 = (lane & 3) * 2;
        float v[4];
        #pragma unroll
        for (int q = 0; q < 4; q++) {
            int k = k0 + (q & 1) + (q >> 1) * 8;
            v[q] = (k < 9) ? w1[k * 64 + n] : ((k == 9) ? b1[n] : 0.0f);
        }
        sB1[nb][lane] = make_uint4(pk_hi(v[0], v[1]), pk_hi(v[2], v[3]),
                                   pk_lo(v[0], v[1]), pk_lo(v[2], v[3]));
    }
    for (int idx = tid; idx < 1024; idx += 128) {
        int kc = idx >> 8, rem = idx & 255;
        int nb = rem >> 5, lane = rem & 31;
        int n = nb * 8 + (lane >> 2);
        int k0 = kc * 16 + (lane & 3) * 2;
        float v0 = w2[k0 * 64 + n],       v1 = w2[(k0 + 1) * 64 + n];
        float v2 = w2[(k0 + 8) * 64 + n], v3 = w2[(k0 + 9) * 64 + n];
        sB2[kc][nb][lane] = make_uint4(pk_hi(v0, v1), pk_hi(v2, v3),
                                       pk_lo(v0, v1), pk_lo(v2, v3));
    }
    {
        int kc = tid >> 5, lane = tid & 31;     // exactly 128 entries
        int n = lane >> 2;
        int k0 = kc * 16 + (lane & 3) * 2;
        float v0 = w3[k0 * 8 + n],       v1 = w3[(k0 + 1) * 8 + n];
        float v2 = w3[(k0 + 8) * 8 + n], v3 = w3[(k0 + 9) * 8 + n];
        sB3[kc][lane] = make_uint4(pk_hi(v0, v1), pk_hi(v2, v3),
                                   pk_lo(v0, v1), pk_lo(v2, v3));
    }
    if (tid < 64) sb2[tid] = b2[tid];
    if (tid >= 64 && tid < 72) sb3[tid - 64] = b3[tid - 64];
    __syncthreads();

    // ---- tile coordinates ----
    const int blk = blockIdx.x;
    const int jt8 = blk & 7;
    const int i   = (blk >> 3) & (SQ - 1);
    const int b   = blk >> 13;
    const int w   = tid >> 5;
    const int lane = tid & 31;
    const int j0  = jt8 * 128 + w * 32;

    const float* cb = coords + (size_t)b * SQ * 3;

    // ---- SH for this warp's 32 pairs (1 per lane), staged as A1 fragment words ----
    {
        const float xi = cb[i * 3 + 0], yi = cb[i * 3 + 1], zi = cb[i * 3 + 2];
        const int j = j0 + lane;
        float rx = xi - cb[j * 3 + 0];
        float ry = yi - cb[j * 3 + 1];
        float rz = zi - cb[j * 3 + 2];
        float nrm = sqrtf(rx * rx + ry * ry + rz * rz);
        float inv1 = __fdividef(1.0f, nrm + 1e-6f);
        float ux = rx * inv1, uy = ry * inv1, uz = rz * inv1;
        float un = nrm * inv1;
        float inv2 = __fdividef(1.0f, fmaxf(un, 1e-6f));
        ux *= inv2; uy *= inv2; uz *= inv2;
        float v[10];
        v[0] = 0.28209479177387814f;
        v[1] = 0.4886025119029199f * ux;
        v[2] = 0.4886025119029199f * uy;
        v[3] = 0.4886025119029199f * uz;
        v[4] = 1.0925484305920792f * ux * uz;
        v[5] = 1.0925484305920792f * ux * uy;
        v[6] = 0.6307831305050401f * (uy * uy - 0.5f * (ux * ux + uz * uz));
        v[7] = 1.0925484305920792f * uy * uz;
        v[8] = 0.5462742152960396f * (uz * uz - ux * ux);
        v[9] = 1.0f;                          // bias slot (b1 folded into W1 k=9)
        #pragma unroll
        for (int kw = 0; kw < 5; kw++) {
            stg[w][0][lane][kw] = pk_hi(v[2 * kw], v[2 * kw + 1]);
            stg[w][1][lane][kw] = pk_lo(v[2 * kw], v[2 * kw + 1]);
        }
        #pragma unroll
        for (int kw = 5; kw < 8; kw++) {
            stg[w][0][lane][kw] = 0u;
            stg[w][1][lane][kw] = 0u;
        }
    }
    __syncwarp();

    const int r0 = lane >> 2;     // row group
    const int qk = lane & 3;      // k/col group

    // A1 fragments for both M-halves (hi + lo)
    uint32_t a1h[2][4], a1l[2][4];
    #pragma unroll
    for (int h = 0; h < 2; h++) {
        int rb = h * 16 + r0;
        a1h[h][0] = stg[w][0][rb][qk];     a1h[h][1] = stg[w][0][rb + 8][qk];
        a1h[h][2] = stg[w][0][rb][qk + 4]; a1h[h][3] = stg[w][0][rb + 8][qk + 4];
        a1l[h][0] = stg[w][1][rb][qk];     a1l[h][1] = stg[w][1][rb + 8][qk];
        a1l[h][2] = stg[w][1][rb][qk + 4]; a1l[h][3] = stg[w][1][rb + 8][qk + 4];
    }

    // ---- GEMM1 + act1 fused per output k-chunk; B-frags shared across halves ----
    uint32_t a2h[2][4][4], a2l[2][4][4];
    #pragma unroll
    for (int kc = 0; kc < 4; kc++) {
        uint4 f0 = sB1[2 * kc][lane], f1 = sB1[2 * kc + 1][lane];
        #pragma unroll
        for (int h = 0; h < 2; h++) {
            float da[4] = {0.f, 0.f, 0.f, 0.f};
            float db[4] = {0.f, 0.f, 0.f, 0.f};
            mma_bf16(da, a1h[h], f0.x, f0.y);
            mma_bf16(db, a1h[h], f1.x, f1.y);
            mma_bf16(da, a1l[h], f0.x, f0.y);
            mma_bf16(db, a1l[h], f1.x, f1.y);
            mma_bf16(da, a1h[h], f0.z, f0.w);
            mma_bf16(db, a1h[h], f1.z, f1.w);
            split2(silu_f(da[0]), silu_f(da[1]), a2h[h][kc][0], a2l[h][kc][0]);
            split2(silu_f(da[2]), silu_f(da[3]), a2h[h][kc][1], a2l[h][kc][1]);
            split2(silu_f(db[0]), silu_f(db[1]), a2h[h][kc][2], a2l[h][kc][2]);
            split2(silu_f(db[2]), silu_f(db[3]), a2h[h][kc][3], a2l[h][kc][3]);
        }
    }

    // ---- GEMM2 -> act2 -> GEMM3 fused per output chunk (d2 never fully live) ----
    float d3[2][4];
    {
        float2 b3v = *(const float2*)&sb3[qk * 2];
        d3[0][0] = b3v.x; d3[0][1] = b3v.y; d3[0][2] = b3v.x; d3[0][3] = b3v.y;
        d3[1][0] = b3v.x; d3[1][1] = b3v.y; d3[1][2] = b3v.x; d3[1][3] = b3v.y;
    }

    #pragma unroll
    for (int ko = 0; ko < 4; ko++) {
        float2 ba = *(const float2*)&sb2[(2 * ko) * 8 + qk * 2];
        float2 bb = *(const float2*)&sb2[(2 * ko + 1) * 8 + qk * 2];
        float d2a[2][4], d2b[2][4];
        #pragma unroll
        for (int h = 0; h < 2; h++) {
            d2a[h][0] = ba.x; d2a[h][1] = ba.y; d2a[h][2] = ba.x; d2a[h][3] = ba.y;
            d2b[h][0] = bb.x; d2b[h][1] = bb.y; d2b[h][2] = bb.x; d2b[h][3] = bb.y;
        }
        #pragma unroll
        for (int ki = 0; ki < 4; ki++) {
            uint4 f0 = sB2[ki][2 * ko][lane], f1 = sB2[ki][2 * ko + 1][lane];
            #pragma unroll
            for (int h = 0; h < 2; h++) {
                mma_bf16(d2a[h], a2h[h][ki], f0.x, f0.y);
                mma_bf16(d2b[h], a2h[h][ki], f1.x, f1.y);
                mma_bf16(d2a[h], a2l[h][ki], f0.x, f0.y);
                mma_bf16(d2b[h], a2l[h][ki], f1.x, f1.y);
                mma_bf16(d2a[h], a2h[h][ki], f0.z, f0.w);
                mma_bf16(d2b[h], a2h[h][ki], f1.z, f1.w);
            }
        }
        // act2 for this output chunk -> A3 fragment of k-chunk ko -> GEMM3 now
        uint4 f3 = sB3[ko][lane];
        #pragma unroll
        for (int h = 0; h < 2; h++) {
            uint32_t th[4], tl[4];
            split2(silu_f(d2a[h][0]), silu_f(d2a[h][1]), th[0], tl[0]);
            split2(silu_f(d2a[h][2]), silu_f(d2a[h][3]), th[1], tl[1]);
            split2(silu_f(d2b[h][0]), silu_f(d2b[h][1]), th[2], tl[2]);
            split2(silu_f(d2b[h][2]), silu_f(d2b[h][3]), th[3], tl[3]);
            mma_bf16(d3[h], th, f3.x, f3.y);
            mma_bf16(d3[h], tl, f3.x, f3.y);
            mma_bf16(d3[h], th, f3.z, f3.w);
        }
    }

    // ---- store: per half, D3 c0/c1 -> (jr, heads 2qk,2qk+1); c2/c3 -> jr+8 ----
    const size_t SS = (size_t)SQ * SQ;
    #pragma unroll
    for (int h = 0; h < 2; h++) {
        const int jr = j0 + h * 16 + r0;
        size_t base = ((size_t)(b * NH + qk * 2)) * SS + (size_t)i * SQ + (size_t)jr;
        out[base]          = d3[h][0];
        out[base + SS]     = d3[h][1];
        out[base + 8]      = d3[h][2];
        out[base + SS + 8] = d3[h][3];
    }
}

extern "C" void kernel_launch(void* const* d_in, const int* in_sizes, int n_in,
                              void* d_out, int out_size) {
    const float* coords = (const float*)d_in[0];
    const float* w1     = (const float*)d_in[1];
    const float* b1     = (const float*)d_in[2];
    const float* w2     = (const float*)d_in[3];
    const float* b2     = (const float*)d_in[4];
    const float* w3     = (const float*)d_in[5];
    const float* b3     = (const float*)d_in[6];
    float* out = (float*)d_out;

    // 2 (batch) * 1024 (i) * 8 (j subtiles of 128) = 16384 blocks, 4 warps each
    shab_mma_kernel<<<16384, 128>>>(coords, w1, b1, w2, b2, w3, b3, out);
}